// round 2
// baseline (speedup 1.0000x reference)
#include <cuda_runtime.h>
#include <cstdint>

#define N_NODES 50000
#define N_EDGES 800000
#define D 64
#define SCAN_THREADS 1024
#define SCAN_CHUNK 49   // ceil(50000/1024)

// -------- device scratch (no allocations allowed) --------
__device__ float g_acc[N_NODES * D];      // N_h accumulator (12.8 MB)
__device__ int   g_deg[N_NODES];          // in-degree histogram
__device__ int   g_off[N_NODES];          // CSR offsets (exclusive scan)
__device__ int   g_cur[N_NODES];          // scatter cursors
__device__ uint2 g_edges[N_EDGES];        // bucketed (src, weight-bits)

// ---------------------------------------------------------------------------
// 1. zero degree counters
// ---------------------------------------------------------------------------
__global__ void zero_deg_kernel() {
    int i = blockIdx.x * blockDim.x + threadIdx.x;
    if (i < N_NODES) g_deg[i] = 0;
}

// ---------------------------------------------------------------------------
// 2. histogram of dst
// ---------------------------------------------------------------------------
__global__ void hist_kernel(const int* __restrict__ dst) {
    int e = blockIdx.x * blockDim.x + threadIdx.x;
    if (e < N_EDGES) atomicAdd(&g_deg[dst[e]], 1);
}

// ---------------------------------------------------------------------------
// 3. exclusive scan of g_deg -> g_off, g_cur  (single block)
// ---------------------------------------------------------------------------
__global__ void scan_kernel() {
    __shared__ int part[SCAN_THREADS];
    int t = threadIdx.x;
    int base = t * SCAN_CHUNK;
    int sum = 0;
#pragma unroll 4
    for (int i = 0; i < SCAN_CHUNK; i++) {
        int idx = base + i;
        if (idx < N_NODES) sum += g_deg[idx];
    }
    part[t] = sum;
    __syncthreads();
    // Hillis-Steele inclusive scan
    for (int off = 1; off < SCAN_THREADS; off <<= 1) {
        int v = (t >= off) ? part[t - off] : 0;
        __syncthreads();
        part[t] += v;
        __syncthreads();
    }
    int run = (t > 0) ? part[t - 1] : 0;
    for (int i = 0; i < SCAN_CHUNK; i++) {
        int idx = base + i;
        if (idx < N_NODES) {
            g_off[idx] = run;
            g_cur[idx] = run;
            run += g_deg[idx];
        }
    }
}

// ---------------------------------------------------------------------------
// 4. scatter edges into dst-buckets as (src, w) with w = ew * outdeg[src]
// ---------------------------------------------------------------------------
__global__ void scatter_kernel(const int* __restrict__ src,
                               const int* __restrict__ dst,
                               const float* __restrict__ ew,
                               const float* __restrict__ outdeg) {
    int e = blockIdx.x * blockDim.x + threadIdx.x;
    if (e >= N_EDGES) return;
    int s = src[e];
    int d = dst[e];
    float w = ew[e] * __ldg(&outdeg[s]);
    int pos = atomicAdd(&g_cur[d], 1);
    g_edges[pos] = make_uint2((unsigned)s, __float_as_uint(w));
}

// ---------------------------------------------------------------------------
// 5. accumulate: per dst node, gather all bucketed sources, sum in registers,
//    single float4 store. 16 lanes per node (one float4 chunk each).
// ---------------------------------------------------------------------------
__global__ void accum_kernel(const float* __restrict__ embed) {
    int gid = blockIdx.x * blockDim.x + threadIdx.x;
    int n = gid >> 4;
    if (n >= N_NODES) return;
    int c = gid & 15;

    int s0 = g_off[n];
    int cnt = g_deg[n];

    float4 a = make_float4(0.f, 0.f, 0.f, 0.f);
    for (int j = s0; j < s0 + cnt; j++) {
        uint2 ed = __ldg(&g_edges[j]);           // broadcast within 16-lane group
        float w = __uint_as_float(ed.y);
        float4 v = __ldg((const float4*)(embed + (size_t)ed.x * D) + c);
        a.x = fmaf(v.x, w, a.x);
        a.y = fmaf(v.y, w, a.y);
        a.z = fmaf(v.z, w, a.z);
        a.w = fmaf(v.w, w, a.w);
    }
    ((float4*)(g_acc + (size_t)n * D))[c] = a;
}

// ---------------------------------------------------------------------------
// 6. out = LeakyReLU((embed + acc*indeg) @ W^T + b)
//    4 rows per warp (4x W smem reuse), packed f32x2 FMAs.
// ---------------------------------------------------------------------------
__device__ __forceinline__ unsigned long long pack_f2(float lo, float hi) {
    unsigned long long r;
    asm("mov.b64 %0, {%1, %2};" : "=l"(r) : "f"(lo), "f"(hi));
    return r;
}
__device__ __forceinline__ void unpack_f2(unsigned long long v, float& lo, float& hi) {
    asm("mov.b64 {%0, %1}, %2;" : "=f"(lo), "=f"(hi) : "l"(v));
}
__device__ __forceinline__ unsigned long long fma_f2(unsigned long long a,
                                                     unsigned long long b,
                                                     unsigned long long c) {
    unsigned long long d;
    asm("fma.rn.f32x2 %0, %1, %2, %3;" : "=l"(d) : "l"(a), "l"(b), "l"(c));
    return d;
}

#define ROWS_PER_WARP 4
#define N_QUADS (N_NODES / ROWS_PER_WARP)   // 12500

__global__ void out_kernel(const float* __restrict__ embed,
                           const float* __restrict__ indeg,
                           const float* __restrict__ W,
                           const float* __restrict__ b,
                           float* __restrict__ out) {
    __shared__ float Wt[D * D];
    __shared__ float bs[D];

    for (int i = threadIdx.x; i < D * D; i += blockDim.x) {
        int j = i >> 6;       // output col
        int k = i & 63;       // input dim
        Wt[k * D + j] = W[i]; // transpose
    }
    if (threadIdx.x < D) bs[threadIdx.x] = b[threadIdx.x];
    __syncthreads();

    int warp = threadIdx.x >> 5;
    int lane = threadIdx.x & 31;
    int wpb = blockDim.x >> 5;
    int nwarps = wpb * gridDim.x;

    for (int q = blockIdx.x * wpb + warp; q < N_QUADS; q += nwarps) {
        int r = q * ROWS_PER_WARP;

        float x0[ROWS_PER_WARP], x1[ROWS_PER_WARP];
#pragma unroll
        for (int rr = 0; rr < ROWS_PER_WARP; rr++) {
            float ind = __ldg(&indeg[r + rr]);
            const float* eb = embed + (size_t)(r + rr) * D;
            const float* ac = g_acc + (size_t)(r + rr) * D;
            x0[rr] = eb[lane]      + ac[lane]      * ind;
            x1[rr] = eb[lane + 32] + ac[lane + 32] * ind;
        }

        unsigned long long bias = pack_f2(bs[2 * lane], bs[2 * lane + 1]);
        unsigned long long acc[ROWS_PER_WARP];
#pragma unroll
        for (int rr = 0; rr < ROWS_PER_WARP; rr++) acc[rr] = bias;

#pragma unroll
        for (int k = 0; k < D; k++) {
            float2 wv = *(const float2*)(Wt + k * D + 2 * lane);
            unsigned long long ww = pack_f2(wv.x, wv.y);
#pragma unroll
            for (int rr = 0; rr < ROWS_PER_WARP; rr++) {
                float xk = __shfl_sync(0xffffffffu,
                                       (k < 32) ? x0[rr] : x1[rr], k & 31);
                acc[rr] = fma_f2(pack_f2(xk, xk), ww, acc[rr]);
            }
        }

#pragma unroll
        for (int rr = 0; rr < ROWS_PER_WARP; rr++) {
            float oa, ob;
            unpack_f2(acc[rr], oa, ob);
            oa = oa > 0.f ? oa : 0.01f * oa;
            ob = ob > 0.f ? ob : 0.01f * ob;
            *(float2*)(out + (size_t)(r + rr) * D + 2 * lane) =
                make_float2(oa, ob);
        }
    }
}

// ---------------------------------------------------------------------------
// kernel_launch
// inputs: 0 entity_embed [N*D] f32, 1 src [E] i32, 2 dst [E] i32,
//         3 edge_weight [E] f32, 4 out_sqrt_degree [N] f32,
//         5 in_sqrt_degree [N] f32, 6 W [D*D] f32, 7 b [D] f32
// ---------------------------------------------------------------------------
extern "C" void kernel_launch(void* const* d_in, const int* in_sizes, int n_in,
                              void* d_out, int out_size) {
    const float* embed  = (const float*)d_in[0];
    const int*   src    = (const int*)d_in[1];
    const int*   dst    = (const int*)d_in[2];
    const float* ew     = (const float*)d_in[3];
    const float* outdeg = (const float*)d_in[4];
    const float* indeg  = (const float*)d_in[5];
    const float* W      = (const float*)d_in[6];
    const float* b      = (const float*)d_in[7];
    float* out = (float*)d_out;

    {   // 1. zero degree counters
        int threads = 256;
        int blocks = (N_NODES + threads - 1) / threads;
        zero_deg_kernel<<<blocks, threads>>>();
    }
    {   // 2. histogram
        int threads = 256;
        int blocks = (N_EDGES + threads - 1) / threads;
        hist_kernel<<<blocks, threads>>>(dst);
    }
    {   // 3. scan
        scan_kernel<<<1, SCAN_THREADS>>>();
    }
    {   // 4. scatter into buckets
        int threads = 256;
        int blocks = (N_EDGES + threads - 1) / threads;
        scatter_kernel<<<blocks, threads>>>(src, dst, ew, outdeg);
    }
    {   // 5. accumulate per dst node
        long long total = (long long)N_NODES * 16;
        int threads = 256;
        int blocks = (int)((total + threads - 1) / threads);
        accum_kernel<<<blocks, threads>>>(embed);
    }
    {   // 6. fused degree-scale + GEMM + LeakyReLU
        int threads = 256;   // 8 warps
        int blocks = 148 * 8;
        out_kernel<<<blocks, threads>>>(embed, indeg, W, b, out);
    }
}

// round 3
// speedup vs baseline: 2.0187x; 2.0187x over previous
#include <cuda_runtime.h>
#include <cstdint>

#define N_NODES 50000
#define N_EDGES 800000
#define D 64
#define CAP 64            // bucket capacity per node (in-deg ~ Poisson(16))

// -------- device scratch (no allocations allowed) --------
__device__ float4 g_acc[N_NODES * (D / 4)];   // N_h * indeg (12.8 MB)
__device__ int    g_cnt[N_NODES];             // per-node cursor
__device__ uint2  g_edges[N_NODES * CAP];     // buckets: (src, w-bits) 25.6 MB
__device__ uint4  g_ovf[N_EDGES];             // overflow: (src, dst, w-bits, -)
__device__ int    g_ovf_cnt;

// ---------------------------------------------------------------------------
// 1. zero per-node cursors + overflow counter
// ---------------------------------------------------------------------------
__global__ void zero_kernel() {
    int i = blockIdx.x * blockDim.x + threadIdx.x;
    if (i < N_NODES) g_cnt[i] = 0;
    if (i == 0) g_ovf_cnt = 0;
}

// ---------------------------------------------------------------------------
// 2. scatter edges into dst-buckets: rec = (src, w = ew * outdeg[src]).
//    4 edges per thread (vectorized loads, 4 independent atomic chains).
// ---------------------------------------------------------------------------
__global__ void scatter_kernel(const int* __restrict__ src,
                               const int* __restrict__ dst,
                               const float* __restrict__ ew,
                               const float* __restrict__ outdeg) {
    int t = blockIdx.x * blockDim.x + threadIdx.x;
    if (t >= N_EDGES / 4) return;

    int4   s4 = ((const int4*)src)[t];
    int4   d4 = ((const int4*)dst)[t];
    float4 w4 = ((const float4*)ew)[t];

    int   ss[4] = {s4.x, s4.y, s4.z, s4.w};
    int   dd[4] = {d4.x, d4.y, d4.z, d4.w};
    float ww[4] = {w4.x, w4.y, w4.z, w4.w};

#pragma unroll
    for (int i = 0; i < 4; i++) {
        float w = ww[i] * __ldg(&outdeg[ss[i]]);
        int pos = atomicAdd(&g_cnt[dd[i]], 1);
        if (pos < CAP) {
            g_edges[dd[i] * CAP + pos] =
                make_uint2((unsigned)ss[i], __float_as_uint(w));
        } else {
            int op = atomicAdd(&g_ovf_cnt, 1);
            g_ovf[op] = make_uint4((unsigned)ss[i], (unsigned)dd[i],
                                   __float_as_uint(w), 0u);
        }
    }
}

// ---------------------------------------------------------------------------
// 3. accumulate: 16 lanes per node; register sum over bucket; one float4
//    store per lane. Unrolled x4 with dual accumulators for MLP.
//    Fuses the in_sqrt_degree scaling.
// ---------------------------------------------------------------------------
__global__ void accum_kernel(const float* __restrict__ embed,
                             const float* __restrict__ indeg) {
    int gid = blockIdx.x * blockDim.x + threadIdx.x;
    int n = gid >> 4;
    if (n >= N_NODES) return;
    int c = gid & 15;

    int cnt = g_cnt[n];
    if (cnt > CAP) cnt = CAP;
    const uint2* bucket = g_edges + (size_t)n * CAP;

    float4 a0 = make_float4(0.f, 0.f, 0.f, 0.f);
    float4 a1 = make_float4(0.f, 0.f, 0.f, 0.f);

    int j = 0;
    for (; j + 4 <= cnt; j += 4) {
        uint2 e0 = __ldg(&bucket[j + 0]);
        uint2 e1 = __ldg(&bucket[j + 1]);
        uint2 e2 = __ldg(&bucket[j + 2]);
        uint2 e3 = __ldg(&bucket[j + 3]);
        float4 v0 = __ldg((const float4*)(embed + (size_t)e0.x * D) + c);
        float4 v1 = __ldg((const float4*)(embed + (size_t)e1.x * D) + c);
        float4 v2 = __ldg((const float4*)(embed + (size_t)e2.x * D) + c);
        float4 v3 = __ldg((const float4*)(embed + (size_t)e3.x * D) + c);
        float w0 = __uint_as_float(e0.y), w1 = __uint_as_float(e1.y);
        float w2 = __uint_as_float(e2.y), w3 = __uint_as_float(e3.y);
        a0.x = fmaf(v0.x, w0, a0.x); a0.y = fmaf(v0.y, w0, a0.y);
        a0.z = fmaf(v0.z, w0, a0.z); a0.w = fmaf(v0.w, w0, a0.w);
        a1.x = fmaf(v1.x, w1, a1.x); a1.y = fmaf(v1.y, w1, a1.y);
        a1.z = fmaf(v1.z, w1, a1.z); a1.w = fmaf(v1.w, w1, a1.w);
        a0.x = fmaf(v2.x, w2, a0.x); a0.y = fmaf(v2.y, w2, a0.y);
        a0.z = fmaf(v2.z, w2, a0.z); a0.w = fmaf(v2.w, w2, a0.w);
        a1.x = fmaf(v3.x, w3, a1.x); a1.y = fmaf(v3.y, w3, a1.y);
        a1.z = fmaf(v3.z, w3, a1.z); a1.w = fmaf(v3.w, w3, a1.w);
    }
    for (; j < cnt; j++) {
        uint2 e = __ldg(&bucket[j]);
        float w = __uint_as_float(e.y);
        float4 v = __ldg((const float4*)(embed + (size_t)e.x * D) + c);
        a0.x = fmaf(v.x, w, a0.x); a0.y = fmaf(v.y, w, a0.y);
        a0.z = fmaf(v.z, w, a0.z); a0.w = fmaf(v.w, w, a0.w);
    }

    float ind = __ldg(&indeg[n]);
    float4 a = make_float4((a0.x + a1.x) * ind, (a0.y + a1.y) * ind,
                           (a0.z + a1.z) * ind, (a0.w + a1.w) * ind);
    g_acc[n * (D / 4) + c] = a;
}

// ---------------------------------------------------------------------------
// 4. overflow fallback (normally empty): red.v4 atomics, scaled by indeg.
// ---------------------------------------------------------------------------
__global__ void overflow_kernel(const float* __restrict__ embed,
                                const float* __restrict__ indeg) {
    int total = g_ovf_cnt;
    int stride = gridDim.x * blockDim.x;
    for (int i = blockIdx.x * blockDim.x + threadIdx.x; i < total; i += stride) {
        uint4 r = g_ovf[i];
        int s = (int)r.x, d = (int)r.y;
        float w = __uint_as_float(r.z) * __ldg(&indeg[d]);
#pragma unroll
        for (int k = 0; k < 16; k++) {
            float4 v = __ldg((const float4*)(embed + (size_t)s * D) + k);
            float* ap = (float*)(g_acc + d * (D / 4) + k);
            asm volatile("red.global.add.v4.f32 [%0], {%1, %2, %3, %4};"
                         :: "l"(ap), "f"(v.x * w), "f"(v.y * w),
                            "f"(v.z * w), "f"(v.w * w) : "memory");
        }
    }
}

// ---------------------------------------------------------------------------
// 5. out = LeakyReLU((embed + acc) @ W^T + b)   [acc already * indeg]
//    4 rows/warp, packed fma.rn.f32x2.
// ---------------------------------------------------------------------------
__device__ __forceinline__ unsigned long long pack_f2(float lo, float hi) {
    unsigned long long r;
    asm("mov.b64 %0, {%1, %2};" : "=l"(r) : "f"(lo), "f"(hi));
    return r;
}
__device__ __forceinline__ void unpack_f2(unsigned long long v, float& lo, float& hi) {
    asm("mov.b64 {%0, %1}, %2;" : "=f"(lo), "=f"(hi) : "l"(v));
}
__device__ __forceinline__ unsigned long long fma_f2(unsigned long long a,
                                                     unsigned long long b,
                                                     unsigned long long c) {
    unsigned long long d;
    asm("fma.rn.f32x2 %0, %1, %2, %3;" : "=l"(d) : "l"(a), "l"(b), "l"(c));
    return d;
}

#define ROWS_PER_WARP 4
#define N_QUADS (N_NODES / ROWS_PER_WARP)

__global__ void out_kernel(const float* __restrict__ embed,
                           const float* __restrict__ W,
                           const float* __restrict__ b,
                           float* __restrict__ out) {
    __shared__ float Wt[D * D];
    __shared__ float bs[D];

    for (int i = threadIdx.x; i < D * D; i += blockDim.x) {
        int j = i >> 6;
        int k = i & 63;
        Wt[k * D + j] = W[i];
    }
    if (threadIdx.x < D) bs[threadIdx.x] = b[threadIdx.x];
    __syncthreads();

    int warp = threadIdx.x >> 5;
    int lane = threadIdx.x & 31;
    int wpb = blockDim.x >> 5;
    int nwarps = wpb * gridDim.x;

    const float* accf = (const float*)g_acc;

    for (int q = blockIdx.x * wpb + warp; q < N_QUADS; q += nwarps) {
        int r = q * ROWS_PER_WARP;

        float x0[ROWS_PER_WARP], x1[ROWS_PER_WARP];
#pragma unroll
        for (int rr = 0; rr < ROWS_PER_WARP; rr++) {
            const float* eb = embed + (size_t)(r + rr) * D;
            const float* ac = accf + (size_t)(r + rr) * D;
            x0[rr] = eb[lane]      + ac[lane];
            x1[rr] = eb[lane + 32] + ac[lane + 32];
        }

        unsigned long long bias = pack_f2(bs[2 * lane], bs[2 * lane + 1]);
        unsigned long long acc[ROWS_PER_WARP];
#pragma unroll
        for (int rr = 0; rr < ROWS_PER_WARP; rr++) acc[rr] = bias;

#pragma unroll
        for (int k = 0; k < D; k++) {
            float2 wv = *(const float2*)(Wt + k * D + 2 * lane);
            unsigned long long ww = pack_f2(wv.x, wv.y);
#pragma unroll
            for (int rr = 0; rr < ROWS_PER_WARP; rr++) {
                float xk = __shfl_sync(0xffffffffu,
                                       (k < 32) ? x0[rr] : x1[rr], k & 31);
                acc[rr] = fma_f2(pack_f2(xk, xk), ww, acc[rr]);
            }
        }

#pragma unroll
        for (int rr = 0; rr < ROWS_PER_WARP; rr++) {
            float oa, ob;
            unpack_f2(acc[rr], oa, ob);
            oa = oa > 0.f ? oa : 0.01f * oa;
            ob = ob > 0.f ? ob : 0.01f * ob;
            *(float2*)(out + (size_t)(r + rr) * D + 2 * lane) =
                make_float2(oa, ob);
        }
    }
}

// ---------------------------------------------------------------------------
// kernel_launch
// ---------------------------------------------------------------------------
extern "C" void kernel_launch(void* const* d_in, const int* in_sizes, int n_in,
                              void* d_out, int out_size) {
    const float* embed  = (const float*)d_in[0];
    const int*   src    = (const int*)d_in[1];
    const int*   dst    = (const int*)d_in[2];
    const float* ew     = (const float*)d_in[3];
    const float* outdeg = (const float*)d_in[4];
    const float* indeg  = (const float*)d_in[5];
    const float* W      = (const float*)d_in[6];
    const float* b      = (const float*)d_in[7];
    float* out = (float*)d_out;

    {   // 1. zero counters
        int threads = 256;
        int blocks = (N_NODES + threads - 1) / threads;
        zero_kernel<<<blocks, threads>>>();
    }
    {   // 2. scatter into fixed-capacity buckets (4 edges/thread)
        int threads = 256;
        int blocks = (N_EDGES / 4 + threads - 1) / threads;
        scatter_kernel<<<blocks, threads>>>(src, dst, ew, outdeg);
    }
    {   // 3. per-node register accumulation (+ indeg scaling)
        long long total = (long long)N_NODES * 16;
        int threads = 256;
        int blocks = (int)((total + threads - 1) / threads);
        accum_kernel<<<blocks, threads>>>(embed, indeg);
    }
    {   // 4. overflow fallback (normally no-op)
        overflow_kernel<<<32, 256>>>(embed, indeg);
    }
    {   // 5. fused GEMM + LeakyReLU
        int threads = 256;
        int blocks = 148 * 8;
        out_kernel<<<blocks, threads>>>(embed, W, b, out);
    }
}